// round 1
// baseline (speedup 1.0000x reference)
#include <cuda_runtime.h>
#include <cuda_bf16.h>
#include <cstdint>

// ============================================================================
// CustomLSTM: B=32, T=2048, I=512, H=512  (4H = 2048 gate rows)
// Phase 1: gx[t][b][g] = x[b][t][:] . Wi[g][:] + bi[g] + bh[g]   (big GEMM)
// Phase 2: persistent scan kernel, 128 CTAs, global spin barrier per step.
// ============================================================================

#define TT 2048
#define BB 32
#define II 512
#define HH 512
#define GG 2048   // 4H

#define NCTA 128
#define WHS_STRIDE 20    // Wh_s[k][lg] row stride (16 + 4 pad)
#define PART_STRIDE 520  // partials stride

// ---- device scratch (module-static; no runtime allocation) ----
__device__ float    g_gx[(size_t)TT * BB * GG];   // 512 MB
__device__ float    g_h[2][HH * BB];              // ping-pong h, transposed [k][b]
__device__ unsigned g_bar;
__device__ volatile unsigned g_gen;

__device__ __forceinline__ float sigf(float x) { return 1.0f / (1.0f + __expf(-x)); }

// ============================================================================
// init: zero h buffer 0 and barrier state (fresh every launch / graph replay)
// ============================================================================
__global__ void lstm_init_kernel() {
    int i = blockIdx.x * blockDim.x + threadIdx.x;
    if (i < HH * BB) g_h[0][i] = 0.0f;
    if (i == 0) { g_bar = 0u; g_gen = 0u; }
}

// ============================================================================
// Phase 1: C[m][n] = A[m][:] . Wi[n][:],  m=(t,b) in 65536, n in 2048, K=512
// 128x128 tile, BK=16, 256 threads, 8x8 micro-tile (4+4 split), reg prefetch.
// ============================================================================
__global__ __launch_bounds__(256) void gemm_gx_kernel(
    const float* __restrict__ x, const float* __restrict__ Wi,
    const float* __restrict__ bi, const float* __restrict__ bh)
{
    __shared__ float As[16][132];
    __shared__ float Bs[16][132];

    const int tid = threadIdx.x;
    const int ntile = blockIdx.x;   // 0..15
    const int mtile = blockIdx.y;   // 0..511
    const int tx = tid & 15, ty = tid >> 4;

    // loader: each thread loads 2 float4 per side per K-iter
    const int lr = tid >> 1;            // row 0..127
    const int lk = (tid & 1) * 8;       // k offset 0 or 8

    const int m0 = mtile * 128 + lr;
    const int ab = m0 & 31, at = m0 >> 5;
    const float* __restrict__ arow = x  + ((size_t)ab * TT + at) * II;
    const float* __restrict__ brow = Wi + (size_t)(ntile * 128 + lr) * II;

    float acc[8][8];
#pragma unroll
    for (int i = 0; i < 8; ++i)
#pragma unroll
        for (int j = 0; j < 8; ++j) acc[i][j] = 0.0f;

    float4 pa0, pa1, pb0, pb1;

    // preload kt = 0
    pa0 = *reinterpret_cast<const float4*>(arow + lk);
    pa1 = *reinterpret_cast<const float4*>(arow + lk + 4);
    pb0 = *reinterpret_cast<const float4*>(brow + lk);
    pb1 = *reinterpret_cast<const float4*>(brow + lk + 4);

    for (int kt = 16; kt <= II; kt += 16) {
        // stage regs -> smem
        As[lk + 0][lr] = pa0.x; As[lk + 1][lr] = pa0.y; As[lk + 2][lr] = pa0.z; As[lk + 3][lr] = pa0.w;
        As[lk + 4][lr] = pa1.x; As[lk + 5][lr] = pa1.y; As[lk + 6][lr] = pa1.z; As[lk + 7][lr] = pa1.w;
        Bs[lk + 0][lr] = pb0.x; Bs[lk + 1][lr] = pb0.y; Bs[lk + 2][lr] = pb0.z; Bs[lk + 3][lr] = pb0.w;
        Bs[lk + 4][lr] = pb1.x; Bs[lk + 5][lr] = pb1.y; Bs[lk + 6][lr] = pb1.z; Bs[lk + 7][lr] = pb1.w;
        __syncthreads();

        // prefetch next tile (overlaps compute)
        if (kt < II) {
            pa0 = *reinterpret_cast<const float4*>(arow + kt + lk);
            pa1 = *reinterpret_cast<const float4*>(arow + kt + lk + 4);
            pb0 = *reinterpret_cast<const float4*>(brow + kt + lk);
            pb1 = *reinterpret_cast<const float4*>(brow + kt + lk + 4);
        }

#pragma unroll
        for (int k = 0; k < 16; ++k) {
            float4 a0 = *reinterpret_cast<const float4*>(&As[k][ty * 4]);
            float4 a1 = *reinterpret_cast<const float4*>(&As[k][64 + ty * 4]);
            float4 b0 = *reinterpret_cast<const float4*>(&Bs[k][tx * 4]);
            float4 b1 = *reinterpret_cast<const float4*>(&Bs[k][64 + tx * 4]);
            float av[8] = {a0.x, a0.y, a0.z, a0.w, a1.x, a1.y, a1.z, a1.w};
            float bv[8] = {b0.x, b0.y, b0.z, b0.w, b1.x, b1.y, b1.z, b1.w};
#pragma unroll
            for (int i = 0; i < 8; ++i)
#pragma unroll
                for (int j = 0; j < 8; ++j) acc[i][j] += av[i] * bv[j];
        }
        __syncthreads();
    }

    // epilogue: + (bi + bh), store
    const int gm0 = mtile * 128;
    const int gn0 = ntile * 128;
    float4 biA = *reinterpret_cast<const float4*>(&bi[gn0 + tx * 4]);
    float4 biB = *reinterpret_cast<const float4*>(&bi[gn0 + 64 + tx * 4]);
    float4 bhA = *reinterpret_cast<const float4*>(&bh[gn0 + tx * 4]);
    float4 bhB = *reinterpret_cast<const float4*>(&bh[gn0 + 64 + tx * 4]);
    float bias0[4] = {biA.x + bhA.x, biA.y + bhA.y, biA.z + bhA.z, biA.w + bhA.w};
    float bias1[4] = {biB.x + bhB.x, biB.y + bhB.y, biB.z + bhB.z, biB.w + bhB.w};

#pragma unroll
    for (int i = 0; i < 8; ++i) {
        int m = gm0 + ((i < 4) ? (ty * 4 + i) : (64 + ty * 4 + (i - 4)));
        float* gxr = g_gx + (size_t)m * GG + gn0;
        float4 o0 = make_float4(acc[i][0] + bias0[0], acc[i][1] + bias0[1],
                                acc[i][2] + bias0[2], acc[i][3] + bias0[3]);
        float4 o1 = make_float4(acc[i][4] + bias1[0], acc[i][5] + bias1[1],
                                acc[i][6] + bias1[2], acc[i][7] + bias1[3]);
        *reinterpret_cast<float4*>(&gxr[tx * 4])      = o0;
        *reinterpret_cast<float4*>(&gxr[64 + tx * 4]) = o1;
    }
}

// ============================================================================
// Phase 2: persistent scan. CTA b owns j in [4b, 4b+4) -> 16 gate rows.
// Wh slice resident in SMEM for all steps; c state in registers; h ping-pong
// in global (transposed hT[k][b]); one global barrier per step.
// ============================================================================
__global__ __launch_bounds__(256) void lstm_scan_kernel(
    const float* __restrict__ Wh,
    float* __restrict__ y, float* __restrict__ hfin, float* __restrict__ cfin)
{
    extern __shared__ float sm[];
    float* whs   = sm;                          // [512][WHS_STRIDE], uses [k][lg]
    float* part  = whs  + 512 * WHS_STRIDE;     // [16][PART_STRIDE]
    float* gates = part + 16 * PART_STRIDE;     // [512]  (lg*32 + b)
    float* hrow  = gates + 512;                 // [32][4] (b, jj)

    const int tid = threadIdx.x;
    const int J0  = blockIdx.x * 4;             // hidden-index base
    const int kc  = tid >> 4;                   // K-chunk 0..15 (32 k each)
    const int pos = tid & 15;
    const int gg  = pos >> 2;                   // gate-type group 0..3
    const int b0  = (pos & 3) * 8;              // batch base
    const int kbase = kc * 32;

    // ---- load Wh slice once: whs[k][lg], lg = q*4 + jj, row = q*512 + J0 + jj
    for (int idx = tid; idx < 16 * 128; idx += 256) {
        int lg = idx >> 7;
        int kq = (idx & 127) * 4;
        int grow = (lg >> 2) * 512 + J0 + (lg & 3);
        float4 v = *reinterpret_cast<const float4*>(&Wh[(size_t)grow * HH + kq]);
        whs[(kq + 0) * WHS_STRIDE + lg] = v.x;
        whs[(kq + 1) * WHS_STRIDE + lg] = v.y;
        whs[(kq + 2) * WHS_STRIDE + lg] = v.z;
        whs[(kq + 3) * WHS_STRIDE + lg] = v.w;
    }

    const int ujj = tid >> 5, ub = tid & 31;    // update-thread mapping (tid<128)
    float c_reg = 0.0f, h_last = 0.0f;
    __syncthreads();

    for (int t = 0; t < TT; ++t) {
        const float* __restrict__ hT  = g_h[t & 1];
        float* __restrict__       hTn = g_h[(t + 1) & 1];

        // prefetch gx for this thread's two outputs (independent of h)
        float gxv0, gxv1;
        {
            int o0 = tid, o1 = tid + 256;
            int lg0 = o0 >> 5, bb0 = o0 & 31;
            int lg1 = o1 >> 5, bb1 = o1 & 31;
            gxv0 = __ldg(&g_gx[((size_t)t * 32 + bb0) * GG + (lg0 >> 2) * 512 + J0 + (lg0 & 3)]);
            gxv1 = __ldg(&g_gx[((size_t)t * 32 + bb1) * GG + (lg1 >> 2) * 512 + J0 + (lg1 & 3)]);
        }

        // ---- partial GEMM: acc[i][j] = sum_{k in chunk} Wh[gg*4+i][k] * h[b0+j][k]
        float acc[4][8];
#pragma unroll
        for (int i = 0; i < 4; ++i)
#pragma unroll
            for (int j = 0; j < 8; ++j) acc[i][j] = 0.0f;

#pragma unroll 8
        for (int kk = 0; kk < 32; ++kk) {
            const int k = kbase + kk;
            const float4 hA = __ldg(reinterpret_cast<const float4*>(hT + k * 32 + b0));
            const float4 hB = __ldg(reinterpret_cast<const float4*>(hT + k * 32 + b0 + 4));
            const float4 wv = *reinterpret_cast<const float4*>(&whs[k * WHS_STRIDE + gg * 4]);
            float hv[8] = {hA.x, hA.y, hA.z, hA.w, hB.x, hB.y, hB.z, hB.w};
            float wr[4] = {wv.x, wv.y, wv.z, wv.w};
#pragma unroll
            for (int i = 0; i < 4; ++i)
#pragma unroll
                for (int j = 0; j < 8; ++j) acc[i][j] += wr[i] * hv[j];
        }

        // write partials
#pragma unroll
        for (int i = 0; i < 4; ++i) {
            int lg = gg * 4 + i;
            float* p = &part[kc * PART_STRIDE + lg * 32 + b0];
            *reinterpret_cast<float4*>(p)     = make_float4(acc[i][0], acc[i][1], acc[i][2], acc[i][3]);
            *reinterpret_cast<float4*>(p + 4) = make_float4(acc[i][4], acc[i][5], acc[i][6], acc[i][7]);
        }
        __syncthreads();

        // ---- reduce over 16 K-chunks, add gx
#pragma unroll
        for (int r = 0; r < 2; ++r) {
            int out = tid + r * 256;
            float s = (r == 0) ? gxv0 : gxv1;
#pragma unroll
            for (int c = 0; c < 16; ++c) s += part[c * PART_STRIDE + out];
            gates[out] = s;
        }
        __syncthreads();

        // ---- elementwise LSTM cell (tid < 128: one (jj, b) each)
        if (tid < 128) {
            float ig = gates[(0 * 4 + ujj) * 32 + ub];
            float fg = gates[(1 * 4 + ujj) * 32 + ub];
            float cg = gates[(2 * 4 + ujj) * 32 + ub];
            float og = gates[(3 * 4 + ujj) * 32 + ub];
            float cn = sigf(fg) * c_reg + sigf(ig) * tanhf(cg);
            float hn = sigf(og) * tanhf(cn);
            c_reg = cn;
            h_last = hn;
            hTn[(J0 + ujj) * 32 + ub] = hn;     // coalesced: 4 rows of 128B
            hrow[ub * 4 + ujj] = hn;
        }
        __syncthreads();

        // y[b][t][J0..J0+3] as float4
        if (tid < 32) {
            float4 v = *reinterpret_cast<const float4*>(&hrow[tid * 4]);
            *reinterpret_cast<float4*>(&y[((size_t)tid * TT + t) * HH + J0]) = v;
        }

        // ---- global barrier between steps
        if (t < TT - 1) {
            __syncthreads();
            if (tid == 0) {
                __threadfence();
                unsigned old = atomicAdd(&g_bar, 1u);
                if (old == (unsigned)NCTA * (unsigned)(t + 1) - 1u) {
                    g_gen = (unsigned)(t + 1);
                } else {
                    while (g_gen < (unsigned)(t + 1)) { }
                }
                __threadfence();
            }
            __syncthreads();
        }
    }

    // finals
    if (tid < 128) {
        hfin[(size_t)ub * HH + J0 + ujj] = h_last;
        cfin[(size_t)ub * HH + J0 + ujj] = c_reg;
    }
}

// ============================================================================
// launch
// ============================================================================
extern "C" void kernel_launch(void* const* d_in, const int* in_sizes, int n_in,
                              void* d_out, int out_size) {
    const float* x  = (const float*)d_in[0];
    const float* Wi = (const float*)d_in[1];
    const float* bi = (const float*)d_in[2];
    const float* Wh = (const float*)d_in[3];
    const float* bh = (const float*)d_in[4];

    float* y    = (float*)d_out;
    float* hfin = y + (size_t)BB * TT * HH;
    float* cfin = hfin + (size_t)BB * HH;

    const int smem_bytes = (512 * WHS_STRIDE + 16 * PART_STRIDE + 512 + 128) * 4;
    cudaFuncSetAttribute(lstm_scan_kernel,
                         cudaFuncAttributeMaxDynamicSharedMemorySize, smem_bytes);

    lstm_init_kernel<<<64, 256>>>();
    gemm_gx_kernel<<<dim3(16, 512), 256>>>(x, Wi, bi, bh);
    lstm_scan_kernel<<<NCTA, 256, smem_bytes>>>(Wh, y, hfin, cfin);
}

// round 3
// speedup vs baseline: 2.2929x; 2.2929x over previous
#include <cuda_runtime.h>
#include <cuda_bf16.h>
#include <cstdint>

// ============================================================================
// CustomLSTM: B=32, T=2048, I=512, H=512 (4H=2048)
// Both phases on tensor cores via mma.sync m16n8k16 bf16 with bf16x3
// decomposition (hi*hi + hi*lo + lo*hi) for ~fp32 accuracy.
// NOTE: harness PTX target is compute_103 (no 'a') -> tcgen05 unavailable.
// ============================================================================

#define TT 2048
#define BB 32
#define II 512
#define HH 512
#define GG 2048

// ---------------- device scratch ----------------
__device__ float    g_gx[(size_t)TT * BB * GG];        // 512 MB
__device__ uint4    g_hb[2][2][2048];                  // ping x {hi,lo} x 32KB of bf16
__device__ int      g_flags[64];

__device__ __forceinline__ float sigf(float x) { return 1.0f / (1.0f + __expf(-x)); }

// pack two floats' bf16 parts; hi2 = {bf16(f1)|bf16(f0)}, lo2 = residuals
__device__ __forceinline__ void split_pair(float f0, float f1, uint32_t& hi2, uint32_t& lo2) {
    uint32_t h;
    asm("cvt.rn.bf16x2.f32 %0, %1, %2;" : "=r"(h) : "f"(f1), "f"(f0));
    float h0 = __uint_as_float(h << 16);
    float h1 = __uint_as_float(h & 0xFFFF0000u);
    asm("cvt.rn.bf16x2.f32 %0, %1, %2;" : "=r"(lo2) : "f"(f1 - h1), "f"(f0 - h0));
    hi2 = h;
}

__device__ __forceinline__ void mma_bf16(float* d, const uint32_t* a, const uint32_t* b) {
    asm volatile(
        "mma.sync.aligned.m16n8k16.row.col.f32.bf16.bf16.f32 "
        "{%0,%1,%2,%3}, {%4,%5,%6,%7}, {%8,%9}, {%0,%1,%2,%3};"
        : "+f"(d[0]), "+f"(d[1]), "+f"(d[2]), "+f"(d[3])
        : "r"(a[0]), "r"(a[1]), "r"(a[2]), "r"(a[3]), "r"(b[0]), "r"(b[1]));
}

// ============================================================================
// init: zero h ping buffer 0 (hi+lo) and flags
// ============================================================================
__global__ void lstm_init_kernel() {
    int i = blockIdx.x * blockDim.x + threadIdx.x;
    if (i < 4096) {
        uint4 z = make_uint4(0u, 0u, 0u, 0u);
        g_hb[0][i >> 11][i & 2047] = z;
    }
    if (i < 64) g_flags[i] = 0;
}

// ============================================================================
// Phase 1: gx[m=(t,b)][n=g] = x . Wi^T + bi + bh
// CTA tile 128x128, K staged 32/iter (16 iters), double-buffered SMEM,
// 8 warps (2x4), warp tile 64x32, bf16x3 HMMA.
// ============================================================================
#define P1_ROWB 80                    // bytes per smem row (32 bf16 + pad)
#define P1_OPB  (128 * P1_ROWB)      // 10240 per operand-half
#define P1_BUFB (4 * P1_OPB)         // 40960 per stage buffer
#define P1_SMEM (2 * P1_BUFB + 512)

__global__ __launch_bounds__(256, 2) void gemm_gx_tc(
    const float* __restrict__ x, const float* __restrict__ Wi,
    const float* __restrict__ bi, const float* __restrict__ bh)
{
    extern __shared__ char sm[];
    float* bias_sm = reinterpret_cast<float*>(sm + 2 * P1_BUFB);

    const int tid = threadIdx.x;
    const int wid = tid >> 5;
    const int lane = tid & 31;
    const int g = lane >> 2;
    const int t4 = lane & 3;
    const int wm = wid >> 2;         // 0..1
    const int wn = wid & 3;          // 0..3

    const int gn0 = blockIdx.x * 128;
    const int gm0 = blockIdx.y * 128;

    if (tid < 128) bias_sm[tid] = bi[gn0 + tid] + bh[gn0 + tid];

    // staging source rows (fixed per thread across K iters)
    // A: 4 float4s, B: 4 float4s
    const float* asrc[4];
    const float* bsrc[4];
    uint32_t adst[4], bdst[4];
#pragma unroll
    for (int it = 0; it < 4; ++it) {
        int aidx = tid + it * 256;           // 0..1023
        int row = aidx >> 3, q = aidx & 7;
        int m = gm0 + row;
        asrc[it] = x + ((size_t)(m & 31) * TT + (m >> 5)) * II + q * 4;
        adst[it] = row * P1_ROWB + q * 8;
        bsrc[it] = Wi + (size_t)(gn0 + row) * II + q * 4;
        bdst[it] = row * P1_ROWB + q * 8;
    }

    float acc[4][4][4];
#pragma unroll
    for (int a = 0; a < 4; ++a)
#pragma unroll
        for (int b = 0; b < 4; ++b)
#pragma unroll
            for (int c = 0; c < 4; ++c) acc[a][b][c] = 0.0f;

    float4 v[8];
#pragma unroll
    for (int it = 0; it < 4; ++it) {
        v[it]     = *reinterpret_cast<const float4*>(asrc[it]);
        v[4 + it] = *reinterpret_cast<const float4*>(bsrc[it]);
    }

    for (int kt = 0; kt < 16; ++kt) {
        char* buf = sm + (kt & 1) * P1_BUFB;
        // convert + STS
#pragma unroll
        for (int it = 0; it < 8; ++it) {
            float4 w = v[it];
            uint32_t h01, l01, h23, l23;
            split_pair(w.x, w.y, h01, l01);
            split_pair(w.z, w.w, h23, l23);
            char* dhi = buf + ((it < 4) ? adst[it] : (2 * P1_OPB + bdst[it - 4]));
            *reinterpret_cast<uint2*>(dhi) = make_uint2(h01, h23);
            *reinterpret_cast<uint2*>(dhi + P1_OPB) = make_uint2(l01, l23);
        }
        __syncthreads();

        if (kt < 15) {
            int ko = (kt + 1) * 32;
#pragma unroll
            for (int it = 0; it < 4; ++it) {
                v[it]     = *reinterpret_cast<const float4*>(asrc[it] + ko);
                v[4 + it] = *reinterpret_cast<const float4*>(bsrc[it] + ko);
            }
        }

        const char* Ah = buf;
        const char* Al = buf + P1_OPB;
        const char* Bh = buf + 2 * P1_OPB;
        const char* Bl = buf + 3 * P1_OPB;

#pragma unroll
        for (int ks = 0; ks < 2; ++ks) {
            const int kb = ks * 32 + 4 * t4;
            uint32_t bhf[4][2], blf[4][2];
#pragma unroll
            for (int nt = 0; nt < 4; ++nt) {
                int n = wn * 32 + nt * 8 + g;
                const char* ph = Bh + n * P1_ROWB + kb;
                const char* pl = Bl + n * P1_ROWB + kb;
                bhf[nt][0] = *reinterpret_cast<const uint32_t*>(ph);
                bhf[nt][1] = *reinterpret_cast<const uint32_t*>(ph + 16);
                blf[nt][0] = *reinterpret_cast<const uint32_t*>(pl);
                blf[nt][1] = *reinterpret_cast<const uint32_t*>(pl + 16);
            }
#pragma unroll
            for (int mt = 0; mt < 4; ++mt) {
                int r = wm * 64 + mt * 16 + g;
                const char* ph = Ah + r * P1_ROWB + kb;
                const char* pl = Al + r * P1_ROWB + kb;
                uint32_t ahf[4], alf[4];
                ahf[0] = *reinterpret_cast<const uint32_t*>(ph);
                ahf[1] = *reinterpret_cast<const uint32_t*>(ph + 8 * P1_ROWB);
                ahf[2] = *reinterpret_cast<const uint32_t*>(ph + 16);
                ahf[3] = *reinterpret_cast<const uint32_t*>(ph + 8 * P1_ROWB + 16);
                alf[0] = *reinterpret_cast<const uint32_t*>(pl);
                alf[1] = *reinterpret_cast<const uint32_t*>(pl + 8 * P1_ROWB);
                alf[2] = *reinterpret_cast<const uint32_t*>(pl + 16);
                alf[3] = *reinterpret_cast<const uint32_t*>(pl + 8 * P1_ROWB + 16);
#pragma unroll
                for (int nt = 0; nt < 4; ++nt) {
                    mma_bf16(acc[mt][nt], ahf, bhf[nt]);
                    mma_bf16(acc[mt][nt], ahf, blf[nt]);
                    mma_bf16(acc[mt][nt], alf, bhf[nt]);
                }
            }
        }
        __syncthreads();
    }

    // epilogue
#pragma unroll
    for (int mt = 0; mt < 4; ++mt) {
        int m0 = gm0 + wm * 64 + mt * 16 + g;
#pragma unroll
        for (int nt = 0; nt < 4; ++nt) {
            int nl = wn * 32 + nt * 8 + 2 * t4;
            float b0v = bias_sm[nl], b1v = bias_sm[nl + 1];
            float2 u0 = make_float2(acc[mt][nt][0] + b0v, acc[mt][nt][1] + b1v);
            float2 u1 = make_float2(acc[mt][nt][2] + b0v, acc[mt][nt][3] + b1v);
            *reinterpret_cast<float2*>(&g_gx[(size_t)m0 * GG + gn0 + nl]) = u0;
            *reinterpret_cast<float2*>(&g_gx[(size_t)(m0 + 8) * GG + gn0 + nl]) = u1;
        }
    }
}

// ============================================================================
// Phase 2: persistent scan, 64 CTAs x 256 thr. CTA owns 8 hidden j.
// Wh slice (32 gate rows) resident in SMEM as bf16 hi/lo. h exchanged via
// global bf16 hi/lo ping-pong; flag-array barrier; HMMA bf16x3 per step.
// ============================================================================
#define WROW 1040                        // bytes per 512-bf16 row (+16B pad)
#define OFF_WHS_HI 0
#define OFF_WHS_LO (32 * WROW)           // 33280
#define OFF_HS_HI  (64 * WROW)           // 66560
#define OFF_HS_LO  (96 * WROW)           // 99840
#define OFF_PART   (128 * WROW)          // 133120
#define PART_SLABW 1152                  // words per warp slab (32 rows x 36)
#define OFF_GATES  (OFF_PART + 8 * PART_SLABW * 4)   // 169984
#define OFF_HROW   (OFF_GATES + 32 * 36 * 4)         // 174592
#define SCAN_SMEM  (OFF_HROW + 32 * 9 * 4 + 64)      // 175808

__global__ __launch_bounds__(256, 1) void lstm_scan_tc(
    const float* __restrict__ Wh,
    float* __restrict__ y, float* __restrict__ hfin, float* __restrict__ cfin)
{
    extern __shared__ char sm[];
    const int tid = threadIdx.x;
    const int wid = tid >> 5;
    const int lane = tid & 31;
    const int g = lane >> 2;
    const int t4 = lane & 3;
    const int J0 = blockIdx.x * 8;

    // ---- Wh slice -> SMEM bf16 hi/lo: row m = q*8+jj, k 0..511
    for (int it = 0; it < 16; ++it) {
        int idx = tid + it * 256;            // 0..4095
        int row = idx >> 7;                  // 0..31
        int kq = (idx & 127) * 4;
        int grow = (row >> 3) * 512 + J0 + (row & 7);
        float4 w = *reinterpret_cast<const float4*>(&Wh[(size_t)grow * HH + kq]);
        uint32_t h01, l01, h23, l23;
        split_pair(w.x, w.y, h01, l01);
        split_pair(w.z, w.w, h23, l23);
        char* dhi = sm + OFF_WHS_HI + row * WROW + kq * 2;
        *reinterpret_cast<uint2*>(dhi) = make_uint2(h01, h23);
        *reinterpret_cast<uint2*>(dhi + (OFF_WHS_LO - OFF_WHS_HI)) = make_uint2(l01, l23);
    }

    // reduce-thread mapping
    const int mr = tid >> 3;                 // 0..31
    const int n4 = (tid & 7) * 4;
    const int qr = mr >> 3, jr = mr & 7;
    // gate-thread mapping
    const int jj = tid >> 5, b = tid & 31;

    float c_reg = 0.0f, h_last = 0.0f;
    volatile int* vflags = (volatile int*)g_flags;
    __syncthreads();

    for (int t = 0; t < TT; ++t) {
        // gx prefetch for reduce outputs [mr][n4..n4+3]
        const float* gxp = g_gx + (size_t)(t * 32) * GG + qr * 512 + J0 + jr;
        float gx0 = __ldg(gxp + (size_t)(n4 + 0) * GG);
        float gx1 = __ldg(gxp + (size_t)(n4 + 1) * GG);
        float gx2 = __ldg(gxp + (size_t)(n4 + 2) * GG);
        float gx3 = __ldg(gxp + (size_t)(n4 + 3) * GG);

        // ---- barrier: wait for h[t]
        if (t > 0) {
            if (tid < 64) {
                while (vflags[tid] < t) __nanosleep(64);
            }
            __threadfence();
        }
        __syncthreads();

        // ---- copy h (bf16 hi/lo) global -> SMEM
        const int p = t & 1;
#pragma unroll
        for (int it = 0; it < 16; ++it) {
            int idx = tid + it * 256;        // 0..4095
            int ver = idx >> 11;             // 0:hi 1:lo
            int c = idx & 2047;
            uint4 val = g_hb[p][ver][c];
            int bb = c >> 6, k0 = (c & 63) * 8;
            char* dst = sm + (ver ? OFF_HS_LO : OFF_HS_HI) + bb * WROW + k0 * 2;
            *reinterpret_cast<uint4*>(dst) = val;
        }
        __syncthreads();

        // ---- MMA: gates[32][32] partial over warp's k-chunk of 64
        float acc[2][4][4];
#pragma unroll
        for (int a = 0; a < 2; ++a)
#pragma unroll
            for (int bb2 = 0; bb2 < 4; ++bb2)
#pragma unroll
                for (int c = 0; c < 4; ++c) acc[a][bb2][c] = 0.0f;

        const int kb = wid * 64;
#pragma unroll
        for (int ks = 0; ks < 4; ++ks) {
            const int koff = (kb + ks * 16 + 2 * t4) * 2;
            uint32_t bhf[4][2], blf[4][2];
#pragma unroll
            for (int nt = 0; nt < 4; ++nt) {
                int n = nt * 8 + g;
                const char* ph = sm + OFF_HS_HI + n * WROW + koff;
                const char* pl = sm + OFF_HS_LO + n * WROW + koff;
                bhf[nt][0] = *reinterpret_cast<const uint32_t*>(ph);
                bhf[nt][1] = *reinterpret_cast<const uint32_t*>(ph + 16);
                blf[nt][0] = *reinterpret_cast<const uint32_t*>(pl);
                blf[nt][1] = *reinterpret_cast<const uint32_t*>(pl + 16);
            }
#pragma unroll
            for (int mt = 0; mt < 2; ++mt) {
                const char* ph = sm + OFF_WHS_HI + (mt * 16 + g) * WROW + koff;
                const char* pl = sm + OFF_WHS_LO + (mt * 16 + g) * WROW + koff;
                uint32_t ahf[4], alf[4];
                ahf[0] = *reinterpret_cast<const uint32_t*>(ph);
                ahf[1] = *reinterpret_cast<const uint32_t*>(ph + 8 * WROW);
                ahf[2] = *reinterpret_cast<const uint32_t*>(ph + 16);
                ahf[3] = *reinterpret_cast<const uint32_t*>(ph + 8 * WROW + 16);
                alf[0] = *reinterpret_cast<const uint32_t*>(pl);
                alf[1] = *reinterpret_cast<const uint32_t*>(pl + 8 * WROW);
                alf[2] = *reinterpret_cast<const uint32_t*>(pl + 16);
                alf[3] = *reinterpret_cast<const uint32_t*>(pl + 8 * WROW + 16);
#pragma unroll
                for (int nt = 0; nt < 4; ++nt) {
                    mma_bf16(acc[mt][nt], ahf, bhf[nt]);
                    mma_bf16(acc[mt][nt], ahf, blf[nt]);
                    mma_bf16(acc[mt][nt], alf, bhf[nt]);
                }
            }
        }

        // ---- partials to SMEM
        {
            char* slab = sm + OFF_PART + wid * (PART_SLABW * 4);
#pragma unroll
            for (int mt = 0; mt < 2; ++mt) {
                int m = mt * 16 + g;
#pragma unroll
                for (int nt = 0; nt < 4; ++nt) {
                    int n = nt * 8 + 2 * t4;
                    *reinterpret_cast<float2*>(slab + (m * 36 + n) * 4) =
                        make_float2(acc[mt][nt][0], acc[mt][nt][1]);
                    *reinterpret_cast<float2*>(slab + ((m + 8) * 36 + n) * 4) =
                        make_float2(acc[mt][nt][2], acc[mt][nt][3]);
                }
            }
        }
        __syncthreads();

        // ---- reduce 8 warps + gx
        {
            float4 s = make_float4(gx0, gx1, gx2, gx3);
#pragma unroll
            for (int w = 0; w < 8; ++w) {
                float4 pp = *reinterpret_cast<const float4*>(
                    sm + OFF_PART + (w * PART_SLABW + mr * 36 + n4) * 4);
                s.x += pp.x; s.y += pp.y; s.z += pp.z; s.w += pp.w;
            }
            *reinterpret_cast<float4*>(sm + OFF_GATES + (mr * 36 + n4) * 4) = s;
        }
        __syncthreads();

        // ---- gate math: thread (jj, b)
        {
            const char* gs = sm + OFF_GATES;
            float ig = *reinterpret_cast<const float*>(gs + ((0 + jj) * 36 + b) * 4);
            float fg = *reinterpret_cast<const float*>(gs + ((8 + jj) * 36 + b) * 4);
            float cg = *reinterpret_cast<const float*>(gs + ((16 + jj) * 36 + b) * 4);
            float og = *reinterpret_cast<const float*>(gs + ((24 + jj) * 36 + b) * 4);
            float cn = sigf(fg) * c_reg + sigf(ig) * tanhf(cg);
            float hn = sigf(og) * tanhf(cn);
            c_reg = cn;
            h_last = hn;
            *reinterpret_cast<float*>(sm + OFF_HROW + (b * 9 + jj) * 4) = hn;
        }
        __syncthreads();

        // ---- writers: tid<32 packs 8 h values -> global bf16 hi/lo + y
        if (tid < 32) {
            const char* hr = sm + OFF_HROW + tid * 36;
            float h0 = *reinterpret_cast<const float*>(hr + 0);
            float h1 = *reinterpret_cast<const float*>(hr + 4);
            float h2 = *reinterpret_cast<const float*>(hr + 8);
            float h3 = *reinterpret_cast<const float*>(hr + 12);
            float h4 = *reinterpret_cast<const float*>(hr + 16);
            float h5 = *reinterpret_cast<const float*>(hr + 20);
            float h6 = *reinterpret_cast<const float*>(hr + 24);
            float h7 = *reinterpret_cast<const float*>(hr + 28);
            uint32_t hi0, lo0, hi1, lo1, hi2, lo2, hi3, lo3;
            split_pair(h0, h1, hi0, lo0);
            split_pair(h2, h3, hi1, lo1);
            split_pair(h4, h5, hi2, lo2);
            split_pair(h6, h7, hi3, lo3);
            int ci = tid * 64 + (J0 >> 3);
            g_hb[p ^ 1][0][ci] = make_uint4(hi0, hi1, hi2, hi3);
            g_hb[p ^ 1][1][ci] = make_uint4(lo0, lo1, lo2, lo3);
            float* yp = y + ((size_t)tid * TT + t) * HH + J0;
            *reinterpret_cast<float4*>(yp)     = make_float4(h0, h1, h2, h3);
            *reinterpret_cast<float4*>(yp + 4) = make_float4(h4, h5, h6, h7);
        }

        // ---- publish
        if (t < TT - 1) {
            __syncthreads();
            if (tid == 0) {
                __threadfence();
                vflags[blockIdx.x] = t + 1;
            }
        }
    }

    hfin[(size_t)b * HH + J0 + jj] = h_last;
    cfin[(size_t)b * HH + J0 + jj] = c_reg;
}

// ============================================================================
// launch
// ============================================================================
extern "C" void kernel_launch(void* const* d_in, const int* in_sizes, int n_in,
                              void* d_out, int out_size) {
    const float* x  = (const float*)d_in[0];
    const float* Wi = (const float*)d_in[1];
    const float* bi = (const float*)d_in[2];
    const float* Wh = (const float*)d_in[3];
    const float* bh = (const float*)d_in[4];

    float* y    = (float*)d_out;
    float* hfin = y + (size_t)BB * TT * HH;
    float* cfin = hfin + (size_t)BB * HH;

    cudaFuncSetAttribute(gemm_gx_tc,
                         cudaFuncAttributeMaxDynamicSharedMemorySize, P1_SMEM);
    cudaFuncSetAttribute(lstm_scan_tc,
                         cudaFuncAttributeMaxDynamicSharedMemorySize, SCAN_SMEM);

    lstm_init_kernel<<<16, 256>>>();
    gemm_gx_tc<<<dim3(16, 512), 256, P1_SMEM>>>(x, Wi, bi, bh);
    lstm_scan_tc<<<64, 256, SCAN_SMEM>>>(Wh, y, hfin, cfin);
}